// round 13
// baseline (speedup 1.0000x reference)
#include <cuda_runtime.h>
#include <cuda_bf16.h>
#include <math.h>
#include <stdint.h>

// Problem constants (fixed shapes from reference)
#define DIN    512
#define BGRAPH 1024
#define NGATE  2048   // 4*DIN
#define KDIM   1024   // 2*DIN
#define TSTEPS 6
#define KCAT   3072   // bf16x3 concatenated K

// ---------------- scratch (device globals; no allocation allowed) ----------
__device__ float g_bsum[NGATE];           // gate-interleaved bias (n' = 4d+gate)
__device__ float g_S[BGRAPH * DIN];       // h state (fp32, for attn q reads)
__device__ float g_c[BGRAPH * DIN];       // cell state
__device__ int   g_seg[BGRAPH + 1];       // segment boundaries
// Row-major bf16 split-cat operands [rows][3072]:
// A classes: [0,1024):hi(S=[h|r]) [1024,2048):lo(S) [2048,3072):hi(S)
// W classes: [0,1024):hi(W)       [1024,2048):hi(W) [2048,3072):lo(W)
// Bext rows are GATE-INTERLEAVED: row n' <-> original gate row (n'&3)*512+(n'>>2)
__device__ __align__(128) __nv_bfloat16 g_Aext[BGRAPH * KCAT];  // 6 MB
__device__ __align__(128) __nv_bfloat16 g_Bext[NGATE * KCAT];   // 12 MB
__device__ __align__(128) __nv_bfloat16 g_Pext[DIN * KCAT];     // 3 MB

// ---------------- helpers ---------------------------------------------------
__device__ __forceinline__ uint32_t smem_u32(const void* p) {
    uint32_t a;
    asm("{ .reg .u64 t; cvta.to.shared.u64 t, %1; cvt.u32.u64 %0, t; }"
        : "=r"(a) : "l"(p));
    return a;
}
__device__ __forceinline__ uint32_t sw128(uint32_t off) {
    return off ^ ((off >> 3) & 0x70);
}
__device__ __forceinline__ void cp16(uint32_t dst, const void* src) {
    asm volatile("cp.async.cg.shared.global [%0], [%1], 16;"
                 :: "r"(dst), "l"(src));
}
#define CP_COMMIT() asm volatile("cp.async.commit_group;")
#define CP_WAIT1()  asm volatile("cp.async.wait_group 1;")
#define CP_WAIT0()  asm volatile("cp.async.wait_group 0;")
#define LDSM_X4(r0, r1, r2, r3, addr) \
    asm volatile("ldmatrix.sync.aligned.m8n8.x4.shared.b16 {%0,%1,%2,%3}, [%4];" \
        : "=r"(r0), "=r"(r1), "=r"(r2), "=r"(r3) : "r"(addr))
#define MMA16816(c, a, b0, b1) \
    asm volatile("mma.sync.aligned.m16n8k16.row.col.f32.bf16.bf16.f32 " \
        "{%0,%1,%2,%3}, {%4,%5,%6,%7}, {%8,%9}, {%0,%1,%2,%3};" \
        : "+f"((c)[0]), "+f"((c)[1]), "+f"((c)[2]), "+f"((c)[3]) \
        : "r"((a)[0]), "r"((a)[1]), "r"((a)[2]), "r"((a)[3]), "r"(b0), "r"(b1))

__device__ __forceinline__ unsigned short bf_hi(float v) {
    return __bfloat16_as_ushort(__float2bfloat16(v));
}
__device__ __forceinline__ unsigned short bf_lo(float v) {
    __nv_bfloat16 h = __float2bfloat16(v);
    return __bfloat16_as_ushort(__float2bfloat16(v - __bfloat162float(h)));
}
__device__ __forceinline__ float sigmoidf_(float v) {
    return 1.f / (1.f + __expf(-v));
}

// ---------------- merged prep (ONE launch -> steers ncu to idx 3 = GEMM) ---
// blocks [0,3072): Bext gate-interleaved; [3072,3840): Pext; [3840,3848): bias
__global__ void prep_all_kernel(const float* __restrict__ Wih,
                                const float* __restrict__ Whh,
                                const float* __restrict__ Wpost,
                                const float* __restrict__ bih,
                                const float* __restrict__ bhh,
                                __nv_bfloat16* __restrict__ Bext,
                                __nv_bfloat16* __restrict__ Pext,
                                float* __restrict__ bsum) {
    int blk = blockIdx.x, tid = threadIdx.x;
    if (blk < 3072) {
        int idx = blk * 256 + tid;
        int row = idx / (KCAT / 8), j = idx % (KCAT / 8);
        int kc0 = j * 8, cls = kc0 >> 10, k0 = kc0 & 1023;
        int orig = (row & 3) * 512 + (row >> 2);         // gate-interleave
        const float* wr = Wih + (size_t)orig * 1024 + k0;
        const float* hr = Whh + (size_t)orig * 512;
        unsigned short u[8];
#pragma unroll
        for (int q = 0; q < 8; q++) {
            float v = wr[q];
            int k = k0 + q;
            if (k < 512) v += hr[k];
            u[q] = (cls < 2) ? bf_hi(v) : bf_lo(v);
        }
        uint4 pk;
        pk.x = (uint32_t)u[0] | ((uint32_t)u[1] << 16);
        pk.y = (uint32_t)u[2] | ((uint32_t)u[3] << 16);
        pk.z = (uint32_t)u[4] | ((uint32_t)u[5] << 16);
        pk.w = (uint32_t)u[6] | ((uint32_t)u[7] << 16);
        *(uint4*)(Bext + (size_t)row * KCAT + kc0) = pk;
    } else if (blk < 3840) {
        int idx = (blk - 3072) * 256 + tid;
        int row = idx / (KCAT / 8), j = idx % (KCAT / 8);
        int kc0 = j * 8, cls = kc0 >> 10, k0 = kc0 & 1023;
        const float* wr = Wpost + (size_t)row * 1024 + k0;
        unsigned short u[8];
#pragma unroll
        for (int q = 0; q < 8; q++) {
            float v = wr[q];
            u[q] = (cls < 2) ? bf_hi(v) : bf_lo(v);
        }
        uint4 pk;
        pk.x = (uint32_t)u[0] | ((uint32_t)u[1] << 16);
        pk.y = (uint32_t)u[2] | ((uint32_t)u[3] << 16);
        pk.z = (uint32_t)u[4] | ((uint32_t)u[5] << 16);
        pk.w = (uint32_t)u[6] | ((uint32_t)u[7] << 16);
        *(uint4*)(Pext + (size_t)row * KCAT + kc0) = pk;
    } else {
        int idx = (blk - 3840) * 256 + tid;
        if (idx < NGATE) {
            int orig = (idx & 3) * 512 + (idx >> 2);
            bsum[idx] = bih[orig] + bhh[orig];
        }
    }
}

// Boundary-scatter segment build; batch = int32 (JAX default) or int64.
__global__ void seg_kernel(const void* __restrict__ batchv, int n,
                           int* __restrict__ seg) {
    const int*       w32 = (const int*)batchv;
    const long long* w64 = (const long long*)batchv;
    const bool is64 = (w32[n - 1] == 0);
    int i = blockIdx.x * 256 + threadIdx.x;
    if (i > n) return;
    long long bi = (i < n) ? (is64 ? w64[i] : (long long)w32[i])
                           : (long long)BGRAPH;
    long long bp = (i > 0) ? (is64 ? w64[i - 1] : (long long)w32[i - 1])
                           : (long long)-1;
    for (long long b = bp + 1; b <= bi; b++) seg[b] = i;
}

// Zero S (0.5M f32), c (0.5M f32), Aext (1.5M u32 words) = 2.5M threads
__global__ void init_zero_kernel(float* __restrict__ S, float* __restrict__ c,
                                 uint32_t* __restrict__ Aw) {
    int idx = blockIdx.x * 256 + threadIdx.x;
    if (idx < BGRAPH * DIN)                  S[idx] = 0.f;
    else if (idx < 2 * BGRAPH * DIN)         c[idx - BGRAPH * DIN] = 0.f;
    else                                     Aw[idx - 2 * BGRAPH * DIN] = 0u;
}

// ---------------- mma.sync bf16 GEMM, 128x128x64, fused-LSTM option --------
// GATED: Bext rows gate-interleaved; epilogue computes LSTM cell, writes
//        c, h->S, and h's bf16x3 classes into Aext (no z tensor at all).
// else:  plain bias + ReLU to C (post_pool).
#define GBM 128
#define GBN 128
#define GBK 64
#define NKI (KCAT / GBK)         // 48
#define STAGEB 16384             // one operand stage: 128 rows x 128 B
#define SMEM_GEMM (4 * STAGEB)   // 64 KB (2 stages x (A+B))

template <bool GATED>
__global__ __launch_bounds__(256, 1)
void gemm_mma_kernel(const __nv_bfloat16* __restrict__ Aext,
                     const __nv_bfloat16* __restrict__ Bx,
                     const float* __restrict__ bias, float* __restrict__ C,
                     int ldc, float* __restrict__ cst, float* __restrict__ S,
                     __nv_bfloat16* __restrict__ Aout) {
    extern __shared__ __align__(128) char sm[];
    const int tid  = threadIdx.x;
    const int wid  = tid >> 5, lane = tid & 31;
    const int wm   = wid & 3;          // m-warp: rows wm*32..+32
    const int wn   = wid >> 2;         // n-warp: cols wn*64..+64
    const int bm   = blockIdx.y * GBM;
    const int bn   = blockIdx.x * GBN;
    const uint32_t sb = smem_u32(sm);

    const __nv_bfloat16* Abase = Aext + (size_t)bm * KCAT;
    const __nv_bfloat16* Bbase = Bx  + (size_t)bn * KCAT;

    float acc[2][8][4] = {};

    const int arow = wm * 32 + (lane & 15);
    const int akb  = ((lane >> 4) & 1) * 16;
    const int nrow = wn * 64 + (lane & 7) + ((lane >> 4) & 1) * 8;  // + g*16
    const int nkb  = ((lane >> 3) & 1) * 16;

    // prologue: stage 0 (A: 1024 chunks, B: 1024 chunks; 8 cp16/thread)
#pragma unroll
    for (int p = 0; p < 4; p++) {
        int ch = p * 256 + tid, r = ch >> 3, c16 = ch & 7;
        cp16(sb + sw128(r * 128 + c16 * 16),
             Abase + (size_t)r * KCAT + c16 * 8);
        cp16(sb + STAGEB + sw128(r * 128 + c16 * 16),
             Bbase + (size_t)r * KCAT + c16 * 8);
    }
    CP_COMMIT();

    for (int i = 0; i < NKI; i++) {
        const uint32_t cur = (i & 1) * (2 * STAGEB);
        if (i + 1 < NKI) {
            const uint32_t nxt = ((i + 1) & 1) * (2 * STAGEB);
            const __nv_bfloat16* An = Abase + (i + 1) * GBK;
            const __nv_bfloat16* Bn = Bbase + (i + 1) * GBK;
#pragma unroll
            for (int p = 0; p < 4; p++) {
                int ch = p * 256 + tid, r = ch >> 3, c16 = ch & 7;
                cp16(sb + nxt + sw128(r * 128 + c16 * 16),
                     An + (size_t)r * KCAT + c16 * 8);
                cp16(sb + nxt + STAGEB + sw128(r * 128 + c16 * 16),
                     Bn + (size_t)r * KCAT + c16 * 8);
            }
            CP_COMMIT();
            CP_WAIT1();
        } else {
            CP_WAIT0();
        }
        __syncthreads();

        const uint32_t abase = sb + cur;
        const uint32_t bbase = sb + cur + STAGEB;
#pragma unroll
        for (int kk = 0; kk < 4; kk++) {
            uint32_t af[2][4], bf[4][4];
#pragma unroll
            for (int mi = 0; mi < 2; mi++)
                LDSM_X4(af[mi][0], af[mi][1], af[mi][2], af[mi][3],
                        abase + sw128((arow + mi * 16) * 128 + kk * 32 + akb));
#pragma unroll
            for (int g = 0; g < 4; g++)
                LDSM_X4(bf[g][0], bf[g][1], bf[g][2], bf[g][3],
                        bbase + sw128((nrow + g * 16) * 128 + kk * 32 + nkb));
#pragma unroll
            for (int mi = 0; mi < 2; mi++)
#pragma unroll
                for (int nj = 0; nj < 8; nj++)
                    MMA16816(acc[mi][nj], af[mi],
                             bf[nj >> 1][(nj & 1) * 2], bf[nj >> 1][(nj & 1) * 2 + 1]);
        }
        __syncthreads();
    }

    // ---- epilogue ----
#pragma unroll
    for (int mi = 0; mi < 2; mi++) {
#pragma unroll
        for (int nj = 0; nj < 8; nj++) {
            const int m0 = bm + wm * 32 + mi * 16 + (lane >> 2);
            const int cn = bn + wn * 64 + nj * 8 + 2 * (lane & 3);
            float b0 = __ldg(bias + cn), b1 = __ldg(bias + cn + 1);
            float v0 = acc[mi][nj][0] + b0, v1 = acc[mi][nj][1] + b1;
            float v2 = acc[mi][nj][2] + b0, v3 = acc[mi][nj][3] + b1;
            if (GATED) {
                // lane pairs (xor 1): even lane&1 holds (i,f), odd holds (g,o)
                float o0 = __shfl_xor_sync(0xffffffffu, v0, 1);
                float o1 = __shfl_xor_sync(0xffffffffu, v1, 1);
                float o2 = __shfl_xor_sync(0xffffffffu, v2, 1);
                float o3 = __shfl_xor_sync(0xffffffffu, v3, 1);
                if ((lane & 1) == 0) {
                    const int d = cn >> 2;          // global 0..511
#pragma unroll
                    for (int rr = 0; rr < 2; rr++) {
                        const int m = m0 + rr * 8;
                        float zi = rr ? v2 : v0, zf = rr ? v3 : v1;
                        float zg = rr ? o2 : o0, zo = rr ? o3 : o1;
                        float cn2 = sigmoidf_(zf) * cst[(size_t)m * DIN + d] +
                                    sigmoidf_(zi) * tanhf(zg);
                        float h = sigmoidf_(zo) * tanhf(cn2);
                        cst[(size_t)m * DIN + d] = cn2;
                        S[(size_t)m * DIN + d] = h;
                        unsigned short* ar =
                            (unsigned short*)(Aout + (size_t)m * KCAT + d);
                        unsigned short hh = bf_hi(h);
                        ar[0]    = hh;
                        ar[1024] = bf_lo(h);
                        ar[2048] = hh;
                    }
                }
            } else {
                v0 = fmaxf(v0, 0.f); v1 = fmaxf(v1, 0.f);
                v2 = fmaxf(v2, 0.f); v3 = fmaxf(v3, 0.f);
                *(float2*)(C + (size_t)m0 * ldc + cn)       = make_float2(v0, v1);
                *(float2*)(C + (size_t)(m0 + 8) * ldc + cn) = make_float2(v2, v3);
            }
        }
    }
}

// ---------------- online-softmax segment attention (single x pass) ---------
__global__ __launch_bounds__(256)
void attn_kernel(const float* __restrict__ x, const float* __restrict__ S,
                 const int* __restrict__ seg, __nv_bfloat16* __restrict__ Aext) {
    __shared__ float  sq[DIN];
    __shared__ float4 sred[8 * 128];
    __shared__ float  swm[8];
    __shared__ float  swd[8];

    const int b = blockIdx.x;
    const int tid = threadIdx.x;
    const int w = tid >> 5, lane = tid & 31;
    const int s = seg[b];
    const int e = seg[b + 1];

    for (int d = tid; d < DIN; d += 256) sq[d] = S[(size_t)b * DIN + d];  // q=h
    __syncthreads();

    const float4* q4 = (const float4*)sq;
    const float4 qa = q4[lane], qb = q4[32 + lane], qc = q4[64 + lane], qd = q4[96 + lane];

    float m = -INFINITY, den = 0.f;
    float4 aa = make_float4(0, 0, 0, 0), ab = aa, ac = aa, ad = aa;

    for (int n = s + w; n < e; n += 8) {
        const float4* xv = (const float4*)(x + (size_t)n * DIN);
        float4 xa = xv[lane], xb = xv[32 + lane], xc = xv[64 + lane], xd = xv[96 + lane];
        float p = xa.x * qa.x + xa.y * qa.y + xa.z * qa.z + xa.w * qa.w;
        p += xb.x * qb.x + xb.y * qb.y + xb.z * qb.z + xb.w * qb.w;
        p += xc.x * qc.x + xc.y * qc.y + xc.z * qc.z + xc.w * qc.w;
        p += xd.x * qd.x + xd.y * qd.y + xd.z * qd.z + xd.w * qd.w;
#pragma unroll
        for (int off = 16; off > 0; off >>= 1)
            p += __shfl_xor_sync(0xffffffffu, p, off);
        float mn = fmaxf(m, p);
        float sc = __expf(m - mn);
        float ex = __expf(p - mn);
        den = den * sc + ex;
        aa.x = aa.x * sc + ex * xa.x; aa.y = aa.y * sc + ex * xa.y;
        aa.z = aa.z * sc + ex * xa.z; aa.w = aa.w * sc + ex * xa.w;
        ab.x = ab.x * sc + ex * xb.x; ab.y = ab.y * sc + ex * xb.y;
        ab.z = ab.z * sc + ex * xb.z; ab.w = ab.w * sc + ex * xb.w;
        ac.x = ac.x * sc + ex * xc.x; ac.y = ac.y * sc + ex * xc.y;
        ac.z = ac.z * sc + ex * xc.z; ac.w = ac.w * sc + ex * xc.w;
        ad.x = ad.x * sc + ex * xd.x; ad.y = ad.y * sc + ex * xd.y;
        ad.z = ad.z * sc + ex * xd.z; ad.w = ad.w * sc + ex * xd.w;
        m = mn;
    }
    sred[w * 128 + lane]      = aa;
    sred[w * 128 + 32 + lane] = ab;
    sred[w * 128 + 64 + lane] = ac;
    sred[w * 128 + 96 + lane] = ad;
    if (lane == 0) { swm[w] = m; swd[w] = den; }
    __syncthreads();

    if (tid < 128) {
        float4 t = make_float4(0, 0, 0, 0);
        if (e > s) {
            float M = -INFINITY;
#pragma unroll
            for (int i = 0; i < 8; i++) M = fmaxf(M, swm[i]);
            float dtot = 0.f;
#pragma unroll
            for (int ww = 0; ww < 8; ww++) {
                float ws = __expf(swm[ww] - M);
                float4 v = sred[ww * 128 + tid];
                t.x += ws * v.x; t.y += ws * v.y;
                t.z += ws * v.z; t.w += ws * v.w;
                dtot += ws * swd[ww];
            }
            float inv = 1.0f / dtot;
            t.x *= inv; t.y *= inv; t.z *= inv; t.w *= inv;
        }
        // bf16x3 r-export into Aext cols 512+4*tid (+class offsets)
        __nv_bfloat16* ar = Aext + (size_t)b * KCAT + 512 + 4 * tid;
        uint2 hi, lo;
        hi.x = (uint32_t)bf_hi(t.x) | ((uint32_t)bf_hi(t.y) << 16);
        hi.y = (uint32_t)bf_hi(t.z) | ((uint32_t)bf_hi(t.w) << 16);
        lo.x = (uint32_t)bf_lo(t.x) | ((uint32_t)bf_lo(t.y) << 16);
        lo.y = (uint32_t)bf_lo(t.z) | ((uint32_t)bf_lo(t.w) << 16);
        *(uint2*)(ar)        = hi;
        *(uint2*)(ar + 1024) = lo;
        *(uint2*)(ar + 2048) = hi;
    }
}

// ---------------- launch ----------------------------------------------------
extern "C" void kernel_launch(void* const* d_in, const int* in_sizes, int n_in,
                              void* d_out, int out_size) {
    const float* x     = (const float*)d_in[0];
    const void*  batch = d_in[1];
    const float* Wih   = (const float*)d_in[2];
    const float* Whh   = (const float*)d_in[3];
    const float* bih   = (const float*)d_in[4];
    const float* bhh   = (const float*)d_in[5];
    const float* Wpost = (const float*)d_in[6];
    const float* bpost = (const float*)d_in[7];
    float*       out   = (float*)d_out;
    const int N = in_sizes[1];

    float *S, *c, *bsum;
    int* seg;
    __nv_bfloat16 *Aext, *Bext, *Pext;
    cudaGetSymbolAddress((void**)&S,    g_S);
    cudaGetSymbolAddress((void**)&c,    g_c);
    cudaGetSymbolAddress((void**)&bsum, g_bsum);
    cudaGetSymbolAddress((void**)&seg,  g_seg);
    cudaGetSymbolAddress((void**)&Aext, g_Aext);
    cudaGetSymbolAddress((void**)&Bext, g_Bext);
    cudaGetSymbolAddress((void**)&Pext, g_Pext);

    cudaFuncSetAttribute(gemm_mma_kernel<true>,
                         cudaFuncAttributeMaxDynamicSharedMemorySize, SMEM_GEMM);
    cudaFuncSetAttribute(gemm_mma_kernel<false>,
                         cudaFuncAttributeMaxDynamicSharedMemorySize, SMEM_GEMM);

    // launch idx 0..2 = prep; idx 3 = first GEMM (ncu captures idx 3)
    prep_all_kernel<<<3848, 256>>>(Wih, Whh, Wpost, bih, bhh, Bext, Pext, bsum);
    seg_kernel<<<(N + 256) / 256, 256>>>(batch, N, seg);
    init_zero_kernel<<<(2 * BGRAPH * DIN + BGRAPH * KCAT / 2) / 256, 256>>>(
        S, c, (uint32_t*)Aext);

    for (int t = 0; t < TSTEPS; t++) {
        gemm_mma_kernel<true><<<dim3(NGATE / GBN, BGRAPH / GBM), 256, SMEM_GEMM>>>(
            Aext, Bext, bsum, nullptr, 0, c, S, Aext);
        attn_kernel<<<BGRAPH, 256>>>(x, S, seg, Aext);
    }
    gemm_mma_kernel<false><<<dim3(DIN / GBN, BGRAPH / GBM), 256, SMEM_GEMM>>>(
        Aext, Pext, bpost, out, DIN, c, S, Aext);
}

// round 14
// speedup vs baseline: 1.0771x; 1.0771x over previous
#include <cuda_runtime.h>
#include <cuda_bf16.h>
#include <math.h>
#include <stdint.h>

// Problem constants (fixed shapes from reference)
#define DIN    512
#define BGRAPH 1024
#define NGATE  2048   // 4*DIN
#define KDIM   1024   // 2*DIN
#define TSTEPS 6
#define KCAT   3072   // bf16x3 concatenated K

// ---------------- scratch (device globals; no allocation allowed) ----------
__device__ float g_bsum[NGATE];           // gate-interleaved bias (n' = 4d+gate)
__device__ float g_S[BGRAPH * DIN];       // h state (fp32, for attn q reads)
__device__ float g_c[BGRAPH * DIN];       // cell state
__device__ int   g_seg[BGRAPH + 1];       // segment boundaries
// Row-major bf16 split-cat operands [rows][3072]:
// A classes: [0,1024):hi(S=[h|r]) [1024,2048):lo(S) [2048,3072):hi(S)
// W classes: [0,1024):hi(W)       [1024,2048):hi(W) [2048,3072):lo(W)
// Bext rows are GATE-INTERLEAVED: row n' <-> original gate row (n'&3)*512+(n'>>2)
__device__ __align__(128) __nv_bfloat16 g_Aext[BGRAPH * KCAT];  // 6 MB
__device__ __align__(128) __nv_bfloat16 g_Bext[NGATE * KCAT];   // 12 MB
__device__ __align__(128) __nv_bfloat16 g_Pext[DIN * KCAT];     // 3 MB

// ---------------- helpers ---------------------------------------------------
__device__ __forceinline__ uint32_t smem_u32(const void* p) {
    uint32_t a;
    asm("{ .reg .u64 t; cvta.to.shared.u64 t, %1; cvt.u32.u64 %0, t; }"
        : "=r"(a) : "l"(p));
    return a;
}
__device__ __forceinline__ uint32_t sw128(uint32_t off) {
    return off ^ ((off >> 3) & 0x70);
}
__device__ __forceinline__ void cp16(uint32_t dst, const void* src) {
    asm volatile("cp.async.cg.shared.global [%0], [%1], 16;"
                 :: "r"(dst), "l"(src));
}
#define CP_COMMIT() asm volatile("cp.async.commit_group;")
#define CP_WAIT1()  asm volatile("cp.async.wait_group 1;")
#define CP_WAIT0()  asm volatile("cp.async.wait_group 0;")
#define LDSM_X4(r0, r1, r2, r3, addr) \
    asm volatile("ldmatrix.sync.aligned.m8n8.x4.shared.b16 {%0,%1,%2,%3}, [%4];" \
        : "=r"(r0), "=r"(r1), "=r"(r2), "=r"(r3) : "r"(addr))
#define MMA16816(c, a, b0, b1) \
    asm volatile("mma.sync.aligned.m16n8k16.row.col.f32.bf16.bf16.f32 " \
        "{%0,%1,%2,%3}, {%4,%5,%6,%7}, {%8,%9}, {%0,%1,%2,%3};" \
        : "+f"((c)[0]), "+f"((c)[1]), "+f"((c)[2]), "+f"((c)[3]) \
        : "r"((a)[0]), "r"((a)[1]), "r"((a)[2]), "r"((a)[3]), "r"(b0), "r"(b1))

__device__ __forceinline__ unsigned short bf_hi(float v) {
    return __bfloat16_as_ushort(__float2bfloat16(v));
}
__device__ __forceinline__ unsigned short bf_lo(float v) {
    __nv_bfloat16 h = __float2bfloat16(v);
    return __bfloat16_as_ushort(__float2bfloat16(v - __bfloat162float(h)));
}
__device__ __forceinline__ float sigmoidf_(float v) {
    return 1.f / (1.f + __expf(-v));
}

// ---------------- merged prep (ONE launch -> ncu idx 3 = first GEMM) -------
// blocks [0,3072): Bext gate-interleaved; [3072,3840): Pext; [3840,3848): bias
__global__ void prep_all_kernel(const float* __restrict__ Wih,
                                const float* __restrict__ Whh,
                                const float* __restrict__ Wpost,
                                const float* __restrict__ bih,
                                const float* __restrict__ bhh,
                                __nv_bfloat16* __restrict__ Bext,
                                __nv_bfloat16* __restrict__ Pext,
                                float* __restrict__ bsum) {
    int blk = blockIdx.x, tid = threadIdx.x;
    if (blk < 3072) {
        int idx = blk * 256 + tid;
        int row = idx / (KCAT / 8), j = idx % (KCAT / 8);
        int kc0 = j * 8, cls = kc0 >> 10, k0 = kc0 & 1023;
        int orig = (row & 3) * 512 + (row >> 2);         // gate-interleave
        const float* wr = Wih + (size_t)orig * 1024 + k0;
        const float* hr = Whh + (size_t)orig * 512;
        unsigned short u[8];
#pragma unroll
        for (int q = 0; q < 8; q++) {
            float v = wr[q];
            int k = k0 + q;
            if (k < 512) v += hr[k];
            u[q] = (cls < 2) ? bf_hi(v) : bf_lo(v);
        }
        uint4 pk;
        pk.x = (uint32_t)u[0] | ((uint32_t)u[1] << 16);
        pk.y = (uint32_t)u[2] | ((uint32_t)u[3] << 16);
        pk.z = (uint32_t)u[4] | ((uint32_t)u[5] << 16);
        pk.w = (uint32_t)u[6] | ((uint32_t)u[7] << 16);
        *(uint4*)(Bext + (size_t)row * KCAT + kc0) = pk;
    } else if (blk < 3840) {
        int idx = (blk - 3072) * 256 + tid;
        int row = idx / (KCAT / 8), j = idx % (KCAT / 8);
        int kc0 = j * 8, cls = kc0 >> 10, k0 = kc0 & 1023;
        const float* wr = Wpost + (size_t)row * 1024 + k0;
        unsigned short u[8];
#pragma unroll
        for (int q = 0; q < 8; q++) {
            float v = wr[q];
            u[q] = (cls < 2) ? bf_hi(v) : bf_lo(v);
        }
        uint4 pk;
        pk.x = (uint32_t)u[0] | ((uint32_t)u[1] << 16);
        pk.y = (uint32_t)u[2] | ((uint32_t)u[3] << 16);
        pk.z = (uint32_t)u[4] | ((uint32_t)u[5] << 16);
        pk.w = (uint32_t)u[6] | ((uint32_t)u[7] << 16);
        *(uint4*)(Pext + (size_t)row * KCAT + kc0) = pk;
    } else {
        int idx = (blk - 3840) * 256 + tid;
        if (idx < NGATE) {
            int orig = (idx & 3) * 512 + (idx >> 2);
            bsum[idx] = bih[orig] + bhh[orig];
        }
    }
}

// Boundary-scatter segment build; batch = int32 (JAX default) or int64.
__global__ void seg_kernel(const void* __restrict__ batchv, int n,
                           int* __restrict__ seg) {
    const int*       w32 = (const int*)batchv;
    const long long* w64 = (const long long*)batchv;
    const bool is64 = (w32[n - 1] == 0);
    int i = blockIdx.x * 256 + threadIdx.x;
    if (i > n) return;
    long long bi = (i < n) ? (is64 ? w64[i] : (long long)w32[i])
                           : (long long)BGRAPH;
    long long bp = (i > 0) ? (is64 ? w64[i - 1] : (long long)w32[i - 1])
                           : (long long)-1;
    for (long long b = bp + 1; b <= bi; b++) seg[b] = i;
}

// Zero S (0.5M f32), c (0.5M f32), Aext (1.5M u32 words) = 2.5M threads
__global__ void init_zero_kernel(float* __restrict__ S, float* __restrict__ c,
                                 uint32_t* __restrict__ Aw) {
    int idx = blockIdx.x * 256 + threadIdx.x;
    if (idx < BGRAPH * DIN)                  S[idx] = 0.f;
    else if (idx < 2 * BGRAPH * DIN)         c[idx - BGRAPH * DIN] = 0.f;
    else                                     Aw[idx - 2 * BGRAPH * DIN] = 0u;
}

// ---------------- mma.sync bf16 GEMM, 128x64x64, fused-LSTM option ---------
// R11-proven tile/occupancy (2 CTAs/SM, 256 CTAs) + R12 fused epilogue.
// GATED: Bext rows gate-interleaved; epilogue computes LSTM cell, writes
//        c, h->S, and h's bf16x3 classes into Aext (no z tensor at all).
// else:  plain bias + ReLU to C (post_pool).
#define GBM 128
#define GBN 64
#define GBK 64
#define NKI (KCAT / GBK)         // 48
#define ASTAGE (GBM * GBK * 2)   // 16384 B
#define BSTAGE (GBN * GBK * 2)   // 8192 B

template <bool GATED>
__global__ __launch_bounds__(256, 2)
void gemm_mma_kernel(const __nv_bfloat16* __restrict__ Aext,
                     const __nv_bfloat16* __restrict__ Bx,
                     const float* __restrict__ bias, float* __restrict__ C,
                     int ldc, float* __restrict__ cst, float* __restrict__ S,
                     __nv_bfloat16* __restrict__ Aout) {
    __shared__ __align__(128) char sA[2 * ASTAGE];   // 32 KB
    __shared__ __align__(128) char sB[2 * BSTAGE];   // 16 KB

    const int tid  = threadIdx.x;
    const int wid  = tid >> 5, lane = tid & 31;
    const int wm   = wid & 3;          // m-warp: rows wm*32..+32
    const int wn   = wid >> 2;         // n-warp: cols wn*32..+32
    const int bm   = blockIdx.y * GBM;
    const int bn   = blockIdx.x * GBN;

    const uint32_t sa = smem_u32(sA);
    const uint32_t sbb = smem_u32(sB);

    const __nv_bfloat16* Abase = Aext + (size_t)bm * KCAT;
    const __nv_bfloat16* Bbase = Bx  + (size_t)bn * KCAT;

    float acc[2][4][4] = {};

    const int arow = wm * 32 + (lane & 15);
    const int akb  = ((lane >> 4) & 1) * 16;
    const int nrow = wn * 32 + (lane & 7) + ((lane >> 4) & 1) * 8;
    const int nkb  = ((lane >> 3) & 1) * 16;

    // prologue: stage 0
#pragma unroll
    for (int p = 0; p < 4; p++) {
        int ch = p * 256 + tid, r = ch >> 3, c16 = ch & 7;
        cp16(sa + sw128(r * 128 + c16 * 16),
             Abase + (size_t)r * KCAT + c16 * 8);
    }
#pragma unroll
    for (int p = 0; p < 2; p++) {
        int ch = p * 256 + tid, r = ch >> 3, c16 = ch & 7;
        cp16(sbb + sw128(r * 128 + c16 * 16),
             Bbase + (size_t)r * KCAT + c16 * 8);
    }
    CP_COMMIT();

    for (int i = 0; i < NKI; i++) {
        const int cur = i & 1;
        if (i + 1 < NKI) {
            const int nxt = (i + 1) & 1;
            const __nv_bfloat16* An = Abase + (i + 1) * GBK;
            const __nv_bfloat16* Bn = Bbase + (i + 1) * GBK;
#pragma unroll
            for (int p = 0; p < 4; p++) {
                int ch = p * 256 + tid, r = ch >> 3, c16 = ch & 7;
                cp16(sa + nxt * ASTAGE + sw128(r * 128 + c16 * 16),
                     An + (size_t)r * KCAT + c16 * 8);
            }
#pragma unroll
            for (int p = 0; p < 2; p++) {
                int ch = p * 256 + tid, r = ch >> 3, c16 = ch & 7;
                cp16(sbb + nxt * BSTAGE + sw128(r * 128 + c16 * 16),
                     Bn + (size_t)r * KCAT + c16 * 8);
            }
            CP_COMMIT();
            CP_WAIT1();
        } else {
            CP_WAIT0();
        }
        __syncthreads();

        const uint32_t abase = sa + cur * ASTAGE;
        const uint32_t bbase = sbb + cur * BSTAGE;
#pragma unroll
        for (int kk = 0; kk < 4; kk++) {
            uint32_t af[2][4], bf[2][4];
#pragma unroll
            for (int mi = 0; mi < 2; mi++)
                LDSM_X4(af[mi][0], af[mi][1], af[mi][2], af[mi][3],
                        abase + sw128((arow + mi * 16) * 128 + kk * 32 + akb));
#pragma unroll
            for (int g = 0; g < 2; g++)
                LDSM_X4(bf[g][0], bf[g][1], bf[g][2], bf[g][3],
                        bbase + sw128((nrow + g * 16) * 128 + kk * 32 + nkb));
#pragma unroll
            for (int mi = 0; mi < 2; mi++)
#pragma unroll
                for (int nj = 0; nj < 4; nj++)
                    MMA16816(acc[mi][nj], af[mi],
                             bf[nj >> 1][(nj & 1) * 2], bf[nj >> 1][(nj & 1) * 2 + 1]);
        }
        __syncthreads();
    }

    // ---- epilogue ----
#pragma unroll
    for (int mi = 0; mi < 2; mi++) {
#pragma unroll
        for (int nj = 0; nj < 4; nj++) {
            const int m0 = bm + wm * 32 + mi * 16 + (lane >> 2);
            const int cn = bn + wn * 32 + nj * 8 + 2 * (lane & 3);
            float b0 = __ldg(bias + cn), b1 = __ldg(bias + cn + 1);
            float v0 = acc[mi][nj][0] + b0, v1 = acc[mi][nj][1] + b1;
            float v2 = acc[mi][nj][2] + b0, v3 = acc[mi][nj][3] + b1;
            if (GATED) {
                // cn = 4d+gate; even (lane&1) holds (i,f) of d, odd holds (g,o)
                float o0 = __shfl_xor_sync(0xffffffffu, v0, 1);
                float o1 = __shfl_xor_sync(0xffffffffu, v1, 1);
                float o2 = __shfl_xor_sync(0xffffffffu, v2, 1);
                float o3 = __shfl_xor_sync(0xffffffffu, v3, 1);
                if ((lane & 1) == 0) {
                    const int d = cn >> 2;          // global 0..511
#pragma unroll
                    for (int rr = 0; rr < 2; rr++) {
                        const int m = m0 + rr * 8;
                        float zi = rr ? v2 : v0, zf = rr ? v3 : v1;
                        float zg = rr ? o2 : o0, zo = rr ? o3 : o1;
                        float cn2 = sigmoidf_(zf) * cst[(size_t)m * DIN + d] +
                                    sigmoidf_(zi) * tanhf(zg);
                        float h = sigmoidf_(zo) * tanhf(cn2);
                        cst[(size_t)m * DIN + d] = cn2;
                        S[(size_t)m * DIN + d] = h;
                        unsigned short* ar =
                            (unsigned short*)(Aout + (size_t)m * KCAT + d);
                        unsigned short hh = bf_hi(h);
                        ar[0]    = hh;
                        ar[1024] = bf_lo(h);
                        ar[2048] = hh;
                    }
                }
            } else {
                v0 = fmaxf(v0, 0.f); v1 = fmaxf(v1, 0.f);
                v2 = fmaxf(v2, 0.f); v3 = fmaxf(v3, 0.f);
                *(float2*)(C + (size_t)m0 * ldc + cn)       = make_float2(v0, v1);
                *(float2*)(C + (size_t)(m0 + 8) * ldc + cn) = make_float2(v2, v3);
            }
        }
    }
}

// ---------------- online-softmax segment attention (single x pass) ---------
__global__ __launch_bounds__(256)
void attn_kernel(const float* __restrict__ x, const float* __restrict__ S,
                 const int* __restrict__ seg, __nv_bfloat16* __restrict__ Aext) {
    __shared__ float  sq[DIN];
    __shared__ float4 sred[8 * 128];
    __shared__ float  swm[8];
    __shared__ float  swd[8];

    const int b = blockIdx.x;
    const int tid = threadIdx.x;
    const int w = tid >> 5, lane = tid & 31;
    const int s = seg[b];
    const int e = seg[b + 1];

    for (int d = tid; d < DIN; d += 256) sq[d] = S[(size_t)b * DIN + d];  // q=h
    __syncthreads();

    const float4* q4 = (const float4*)sq;
    const float4 qa = q4[lane], qb = q4[32 + lane], qc = q4[64 + lane], qd = q4[96 + lane];

    float m = -INFINITY, den = 0.f;
    float4 aa = make_float4(0, 0, 0, 0), ab = aa, ac = aa, ad = aa;

    for (int n = s + w; n < e; n += 8) {
        const float4* xv = (const float4*)(x + (size_t)n * DIN);
        float4 xa = xv[lane], xb = xv[32 + lane], xc = xv[64 + lane], xd = xv[96 + lane];
        float p = xa.x * qa.x + xa.y * qa.y + xa.z * qa.z + xa.w * qa.w;
        p += xb.x * qb.x + xb.y * qb.y + xb.z * qb.z + xb.w * qb.w;
        p += xc.x * qc.x + xc.y * qc.y + xc.z * qc.z + xc.w * qc.w;
        p += xd.x * qd.x + xd.y * qd.y + xd.z * qd.z + xd.w * qd.w;
#pragma unroll
        for (int off = 16; off > 0; off >>= 1)
            p += __shfl_xor_sync(0xffffffffu, p, off);
        float mn = fmaxf(m, p);
        float sc = __expf(m - mn);
        float ex = __expf(p - mn);
        den = den * sc + ex;
        aa.x = aa.x * sc + ex * xa.x; aa.y = aa.y * sc + ex * xa.y;
        aa.z = aa.z * sc + ex * xa.z; aa.w = aa.w * sc + ex * xa.w;
        ab.x = ab.x * sc + ex * xb.x; ab.y = ab.y * sc + ex * xb.y;
        ab.z = ab.z * sc + ex * xb.z; ab.w = ab.w * sc + ex * xb.w;
        ac.x = ac.x * sc + ex * xc.x; ac.y = ac.y * sc + ex * xc.y;
        ac.z = ac.z * sc + ex * xc.z; ac.w = ac.w * sc + ex * xc.w;
        ad.x = ad.x * sc + ex * xd.x; ad.y = ad.y * sc + ex * xd.y;
        ad.z = ad.z * sc + ex * xd.z; ad.w = ad.w * sc + ex * xd.w;
        m = mn;
    }
    sred[w * 128 + lane]      = aa;
    sred[w * 128 + 32 + lane] = ab;
    sred[w * 128 + 64 + lane] = ac;
    sred[w * 128 + 96 + lane] = ad;
    if (lane == 0) { swm[w] = m; swd[w] = den; }
    __syncthreads();

    if (tid < 128) {
        float4 t = make_float4(0, 0, 0, 0);
        if (e > s) {
            float M = -INFINITY;
#pragma unroll
            for (int i = 0; i < 8; i++) M = fmaxf(M, swm[i]);
            float dtot = 0.f;
#pragma unroll
            for (int ww = 0; ww < 8; ww++) {
                float ws = __expf(swm[ww] - M);
                float4 v = sred[ww * 128 + tid];
                t.x += ws * v.x; t.y += ws * v.y;
                t.z += ws * v.z; t.w += ws * v.w;
                dtot += ws * swd[ww];
            }
            float inv = 1.0f / dtot;
            t.x *= inv; t.y *= inv; t.z *= inv; t.w *= inv;
        }
        // bf16x3 r-export into Aext cols 512+4*tid (+class offsets)
        __nv_bfloat16* ar = Aext + (size_t)b * KCAT + 512 + 4 * tid;
        uint2 hi, lo;
        hi.x = (uint32_t)bf_hi(t.x) | ((uint32_t)bf_hi(t.y) << 16);
        hi.y = (uint32_t)bf_hi(t.z) | ((uint32_t)bf_hi(t.w) << 16);
        lo.x = (uint32_t)bf_lo(t.x) | ((uint32_t)bf_lo(t.y) << 16);
        lo.y = (uint32_t)bf_lo(t.z) | ((uint32_t)bf_lo(t.w) << 16);
        *(uint2*)(ar)        = hi;
        *(uint2*)(ar + 1024) = lo;
        *(uint2*)(ar + 2048) = hi;
    }
}

// ---------------- launch ----------------------------------------------------
extern "C" void kernel_launch(void* const* d_in, const int* in_sizes, int n_in,
                              void* d_out, int out_size) {
    const float* x     = (const float*)d_in[0];
    const void*  batch = d_in[1];
    const float* Wih   = (const float*)d_in[2];
    const float* Whh   = (const float*)d_in[3];
    const float* bih   = (const float*)d_in[4];
    const float* bhh   = (const float*)d_in[5];
    const float* Wpost = (const float*)d_in[6];
    const float* bpost = (const float*)d_in[7];
    float*       out   = (float*)d_out;
    const int N = in_sizes[1];

    float *S, *c, *bsum;
    int* seg;
    __nv_bfloat16 *Aext, *Bext, *Pext;
    cudaGetSymbolAddress((void**)&S,    g_S);
    cudaGetSymbolAddress((void**)&c,    g_c);
    cudaGetSymbolAddress((void**)&bsum, g_bsum);
    cudaGetSymbolAddress((void**)&seg,  g_seg);
    cudaGetSymbolAddress((void**)&Aext, g_Aext);
    cudaGetSymbolAddress((void**)&Bext, g_Bext);
    cudaGetSymbolAddress((void**)&Pext, g_Pext);

    // launch idx 0..2 = prep; idx 3 = first GEMM (ncu captures idx 3)
    prep_all_kernel<<<3848, 256>>>(Wih, Whh, Wpost, bih, bhh, Bext, Pext, bsum);
    seg_kernel<<<(N + 256) / 256, 256>>>(batch, N, seg);
    init_zero_kernel<<<(2 * BGRAPH * DIN + BGRAPH * KCAT / 2) / 256, 256>>>(
        S, c, (uint32_t*)Aext);

    for (int t = 0; t < TSTEPS; t++) {
        // 32 x 8 = 256 CTAs, 2/SM — the R11-measured-good shape
        gemm_mma_kernel<true><<<dim3(NGATE / GBN, BGRAPH / GBM), 256>>>(
            Aext, Bext, bsum, nullptr, 0, c, S, Aext);
        attn_kernel<<<BGRAPH, 256>>>(x, S, seg, Aext);
    }
    gemm_mma_kernel<false><<<dim3(DIN / GBN, BGRAPH / GBM), 256>>>(
        Aext, Pext, bpost, out, DIN, c, S, Aext);
}

// round 15
// speedup vs baseline: 1.1685x; 1.0848x over previous
#include <cuda_runtime.h>
#include <cuda_bf16.h>
#include <math.h>
#include <stdint.h>

// Problem constants (fixed shapes from reference)
#define DIN    512
#define BGRAPH 1024
#define NGATE  2048   // 4*DIN
#define KDIM   1024   // 2*DIN
#define TSTEPS 6
#define KCAT   3072   // bf16x3 concatenated K

// ---------------- scratch (device globals; no allocation allowed) ----------
__device__ float g_bsum[NGATE];           // bih+bhh (natural gate layout)
__device__ float g_S[BGRAPH * DIN];       // h state (fp32, attn q reads)
__device__ float g_c[BGRAPH * DIN];       // cell state
__device__ float g_z[BGRAPH * NGATE];     // pre-activation gates
__device__ int   g_seg[BGRAPH + 1];       // segment boundaries
// Row-major bf16 split-cat operands [rows][3072]:
// A classes: [0,1024):hi(S=[h|r]) [1024,2048):lo(S) [2048,3072):hi(S)
// W classes: [0,1024):hi(W)       [1024,2048):hi(W) [2048,3072):lo(W)
__device__ __align__(128) __nv_bfloat16 g_Aext[BGRAPH * KCAT];  // 6 MB
__device__ __align__(128) __nv_bfloat16 g_Bext[NGATE * KCAT];   // 12 MB
__device__ __align__(128) __nv_bfloat16 g_Pext[DIN * KCAT];     // 3 MB

// ---------------- helpers ---------------------------------------------------
__device__ __forceinline__ uint32_t smem_u32(const void* p) {
    uint32_t a;
    asm("{ .reg .u64 t; cvta.to.shared.u64 t, %1; cvt.u32.u64 %0, t; }"
        : "=r"(a) : "l"(p));
    return a;
}
__device__ __forceinline__ uint32_t sw128(uint32_t off) {
    return off ^ ((off >> 3) & 0x70);
}
__device__ __forceinline__ void cp16(uint32_t dst, const void* src) {
    asm volatile("cp.async.cg.shared.global [%0], [%1], 16;"
                 :: "r"(dst), "l"(src));
}
#define CP_COMMIT() asm volatile("cp.async.commit_group;")
#define CP_WAIT2()  asm volatile("cp.async.wait_group 2;")
#define CP_WAIT1()  asm volatile("cp.async.wait_group 1;")
#define CP_WAIT0()  asm volatile("cp.async.wait_group 0;")
#define LDSM_X4(r0, r1, r2, r3, addr) \
    asm volatile("ldmatrix.sync.aligned.m8n8.x4.shared.b16 {%0,%1,%2,%3}, [%4];" \
        : "=r"(r0), "=r"(r1), "=r"(r2), "=r"(r3) : "r"(addr))
#define MMA16816(c, a, b0, b1) \
    asm volatile("mma.sync.aligned.m16n8k16.row.col.f32.bf16.bf16.f32 " \
        "{%0,%1,%2,%3}, {%4,%5,%6,%7}, {%8,%9}, {%0,%1,%2,%3};" \
        : "+f"((c)[0]), "+f"((c)[1]), "+f"((c)[2]), "+f"((c)[3]) \
        : "r"((a)[0]), "r"((a)[1]), "r"((a)[2]), "r"((a)[3]), "r"(b0), "r"(b1))

__device__ __forceinline__ unsigned short bf_hi(float v) {
    return __bfloat16_as_ushort(__float2bfloat16(v));
}
__device__ __forceinline__ unsigned short bf_lo(float v) {
    __nv_bfloat16 h = __float2bfloat16(v);
    return __bfloat16_as_ushort(__float2bfloat16(v - __bfloat162float(h)));
}

// ---------------- merged prep (ONE launch -> ncu idx 3 = first GEMM) -------
// blocks [0,3072): Bext (natural rows); [3072,3840): Pext; [3840,3848): bias
__global__ void prep_all_kernel(const float* __restrict__ Wih,
                                const float* __restrict__ Whh,
                                const float* __restrict__ Wpost,
                                const float* __restrict__ bih,
                                const float* __restrict__ bhh,
                                __nv_bfloat16* __restrict__ Bext,
                                __nv_bfloat16* __restrict__ Pext,
                                float* __restrict__ bsum) {
    int blk = blockIdx.x, tid = threadIdx.x;
    if (blk < 3072) {
        int idx = blk * 256 + tid;
        int row = idx / (KCAT / 8), j = idx % (KCAT / 8);
        int kc0 = j * 8, cls = kc0 >> 10, k0 = kc0 & 1023;
        const float* wr = Wih + (size_t)row * 1024 + k0;
        const float* hr = Whh + (size_t)row * 512;
        unsigned short u[8];
#pragma unroll
        for (int q = 0; q < 8; q++) {
            float v = wr[q];
            int k = k0 + q;
            if (k < 512) v += hr[k];
            u[q] = (cls < 2) ? bf_hi(v) : bf_lo(v);
        }
        uint4 pk;
        pk.x = (uint32_t)u[0] | ((uint32_t)u[1] << 16);
        pk.y = (uint32_t)u[2] | ((uint32_t)u[3] << 16);
        pk.z = (uint32_t)u[4] | ((uint32_t)u[5] << 16);
        pk.w = (uint32_t)u[6] | ((uint32_t)u[7] << 16);
        *(uint4*)(Bext + (size_t)row * KCAT + kc0) = pk;
    } else if (blk < 3840) {
        int idx = (blk - 3072) * 256 + tid;
        int row = idx / (KCAT / 8), j = idx % (KCAT / 8);
        int kc0 = j * 8, cls = kc0 >> 10, k0 = kc0 & 1023;
        const float* wr = Wpost + (size_t)row * 1024 + k0;
        unsigned short u[8];
#pragma unroll
        for (int q = 0; q < 8; q++) {
            float v = wr[q];
            u[q] = (cls < 2) ? bf_hi(v) : bf_lo(v);
        }
        uint4 pk;
        pk.x = (uint32_t)u[0] | ((uint32_t)u[1] << 16);
        pk.y = (uint32_t)u[2] | ((uint32_t)u[3] << 16);
        pk.z = (uint32_t)u[4] | ((uint32_t)u[5] << 16);
        pk.w = (uint32_t)u[6] | ((uint32_t)u[7] << 16);
        *(uint4*)(Pext + (size_t)row * KCAT + kc0) = pk;
    } else {
        int idx = (blk - 3840) * 256 + tid;
        if (idx < NGATE) bsum[idx] = bih[idx] + bhh[idx];
    }
}

// Boundary-scatter segment build; batch = int32 (JAX default) or int64.
__global__ void seg_kernel(const void* __restrict__ batchv, int n,
                           int* __restrict__ seg) {
    const int*       w32 = (const int*)batchv;
    const long long* w64 = (const long long*)batchv;
    const bool is64 = (w32[n - 1] == 0);
    int i = blockIdx.x * 256 + threadIdx.x;
    if (i > n) return;
    long long bi = (i < n) ? (is64 ? w64[i] : (long long)w32[i])
                           : (long long)BGRAPH;
    long long bp = (i > 0) ? (is64 ? w64[i - 1] : (long long)w32[i - 1])
                           : (long long)-1;
    for (long long b = bp + 1; b <= bi; b++) seg[b] = i;
}

// Zero S (0.5M f32), c (0.5M f32), Aext (1.5M u32 words) = 2.5M threads
__global__ void init_zero_kernel(float* __restrict__ S, float* __restrict__ c,
                                 uint32_t* __restrict__ Aw) {
    int idx = blockIdx.x * 256 + threadIdx.x;
    if (idx < BGRAPH * DIN)                  S[idx] = 0.f;
    else if (idx < 2 * BGRAPH * DIN)         c[idx - BGRAPH * DIN] = 0.f;
    else                                     Aw[idx - 2 * BGRAPH * DIN] = 0u;
}

// ---------------- mma.sync bf16 GEMM, 128x64x64, 3-STAGE pipeline ----------
// C[M,N] = Aext[M,KCAT] @ Bext[N,KCAT]^T + bias[N]  (opt ReLU)
#define GBM 128
#define GBN 64
#define GBK 64
#define NKI (KCAT / GBK)          // 48
#define ASTAGE (GBM * GBK * 2)    // 16384 B
#define BSTAGE (GBN * GBK * 2)    // 8192 B
#define STG_STRIDE (ASTAGE + BSTAGE)   // 24576 B per stage
#define SMEM3 (3 * STG_STRIDE)         // 73728 B dynamic

template <bool RELU>
__global__ __launch_bounds__(256, 2)
void gemm_mma_kernel(const __nv_bfloat16* __restrict__ Aext,
                     const __nv_bfloat16* __restrict__ Bx,
                     const float* __restrict__ bias, float* __restrict__ C,
                     int ldc) {
    extern __shared__ __align__(128) char sm3[];
    const int tid  = threadIdx.x;
    const int wid  = tid >> 5, lane = tid & 31;
    const int wm   = wid & 3;          // m-warp: rows wm*32..+32
    const int wn   = wid >> 2;         // n-warp: cols wn*32..+32
    const int bm   = blockIdx.y * GBM;
    const int bn   = blockIdx.x * GBN;
    const uint32_t sb = smem_u32(sm3);

    const __nv_bfloat16* Abase = Aext + (size_t)bm * KCAT;
    const __nv_bfloat16* Bbase = Bx  + (size_t)bn * KCAT;

    float acc[2][4][4] = {};

    const int arow = wm * 32 + (lane & 15);
    const int akb  = ((lane >> 4) & 1) * 16;
    const int nrow = wn * 32 + (lane & 7) + ((lane >> 4) & 1) * 8;
    const int nkb  = ((lane >> 3) & 1) * 16;

    // per-thread load coordinates
    const int ar4 = tid >> 3, ac4 = tid & 7;      // A: 4 chunks via p*256
    // prologue: stages 0 and 1 as separate commit groups
#pragma unroll
    for (int s = 0; s < 2; s++) {
        const uint32_t st = sb + s * STG_STRIDE;
        const __nv_bfloat16* An = Abase + s * GBK;
        const __nv_bfloat16* Bn = Bbase + s * GBK;
#pragma unroll
        for (int p = 0; p < 4; p++) {
            int r = p * 32 + ar4;
            cp16(st + sw128(r * 128 + ac4 * 16), An + (size_t)r * KCAT + ac4 * 8);
        }
#pragma unroll
        for (int p = 0; p < 2; p++) {
            int r = p * 32 + ar4;
            cp16(st + ASTAGE + sw128(r * 128 + ac4 * 16),
                 Bn + (size_t)r * KCAT + ac4 * 8);
        }
        CP_COMMIT();
    }

    int cur_s = 0;
    for (int i = 0; i < NKI; i++) {
        if (i + 2 < NKI) {
            const int ns = (cur_s + 2 >= 3) ? cur_s - 1 : cur_s + 2;
            const uint32_t st = sb + ns * STG_STRIDE;
            const __nv_bfloat16* An = Abase + (i + 2) * GBK;
            const __nv_bfloat16* Bn = Bbase + (i + 2) * GBK;
#pragma unroll
            for (int p = 0; p < 4; p++) {
                int r = p * 32 + ar4;
                cp16(st + sw128(r * 128 + ac4 * 16),
                     An + (size_t)r * KCAT + ac4 * 8);
            }
#pragma unroll
            for (int p = 0; p < 2; p++) {
                int r = p * 32 + ar4;
                cp16(st + ASTAGE + sw128(r * 128 + ac4 * 16),
                     Bn + (size_t)r * KCAT + ac4 * 8);
            }
            CP_COMMIT();
            CP_WAIT2();
        } else if (i + 1 < NKI) {
            CP_WAIT1();
        } else {
            CP_WAIT0();
        }
        __syncthreads();

        const uint32_t abase = sb + cur_s * STG_STRIDE;
        const uint32_t bbase = abase + ASTAGE;
#pragma unroll
        for (int kk = 0; kk < 4; kk++) {
            uint32_t af[2][4], bf[2][4];
#pragma unroll
            for (int mi = 0; mi < 2; mi++)
                LDSM_X4(af[mi][0], af[mi][1], af[mi][2], af[mi][3],
                        abase + sw128((arow + mi * 16) * 128 + kk * 32 + akb));
#pragma unroll
            for (int g = 0; g < 2; g++)
                LDSM_X4(bf[g][0], bf[g][1], bf[g][2], bf[g][3],
                        bbase + sw128((nrow + g * 16) * 128 + kk * 32 + nkb));
#pragma unroll
            for (int mi = 0; mi < 2; mi++)
#pragma unroll
                for (int nj = 0; nj < 4; nj++)
                    MMA16816(acc[mi][nj], af[mi],
                             bf[nj >> 1][(nj & 1) * 2], bf[nj >> 1][(nj & 1) * 2 + 1]);
        }
        __syncthreads();
        cur_s = (cur_s + 1 == 3) ? 0 : cur_s + 1;
    }

    // ---- epilogue: bias (+ReLU), plain stores ----
#pragma unroll
    for (int mi = 0; mi < 2; mi++) {
#pragma unroll
        for (int nj = 0; nj < 4; nj++) {
            const int m0 = bm + wm * 32 + mi * 16 + (lane >> 2);
            const int cn = bn + wn * 32 + nj * 8 + 2 * (lane & 3);
            float b0 = __ldg(bias + cn), b1 = __ldg(bias + cn + 1);
            float v0 = acc[mi][nj][0] + b0, v1 = acc[mi][nj][1] + b1;
            float v2 = acc[mi][nj][2] + b0, v3 = acc[mi][nj][3] + b1;
            if (RELU) {
                v0 = fmaxf(v0, 0.f); v1 = fmaxf(v1, 0.f);
                v2 = fmaxf(v2, 0.f); v3 = fmaxf(v3, 0.f);
            }
            *(float2*)(C + (size_t)m0 * ldc + cn)       = make_float2(v0, v1);
            *(float2*)(C + (size_t)(m0 + 8) * ldc + cn) = make_float2(v2, v3);
        }
    }
}

// ---------------- LSTM cell + fused bf16x3 h-export (R11-proven) -----------
__global__ __launch_bounds__(256)
void lstm_kernel(const float* __restrict__ z, float* __restrict__ c,
                 float* __restrict__ S, __nv_bfloat16* __restrict__ Aext) {
    int T = blockIdx.x * 256 + threadIdx.x;     // < 262144
    int m = T >> 8, d = (T & 255) * 2;
    const float* zr = z + (size_t)m * NGATE;
    float2 zi = *(const float2*)(zr + d);
    float2 zf = *(const float2*)(zr + 512 + d);
    float2 zg = *(const float2*)(zr + 1024 + d);
    float2 zo = *(const float2*)(zr + 1536 + d);
    float2 cc = *(float2*)(c + (size_t)m * DIN + d);

    float si0 = 1.f / (1.f + __expf(-zi.x)), si1 = 1.f / (1.f + __expf(-zi.y));
    float sf0 = 1.f / (1.f + __expf(-zf.x)), sf1 = 1.f / (1.f + __expf(-zf.y));
    float so0 = 1.f / (1.f + __expf(-zo.x)), so1 = 1.f / (1.f + __expf(-zo.y));
    float cn0 = sf0 * cc.x + si0 * tanhf(zg.x);
    float cn1 = sf1 * cc.y + si1 * tanhf(zg.y);
    float h0 = so0 * tanhf(cn0);
    float h1 = so1 * tanhf(cn1);

    *(float2*)(c + (size_t)m * DIN + d) = make_float2(cn0, cn1);
    *(float2*)(S + (size_t)m * DIN + d) = make_float2(h0, h1);

    __nv_bfloat16* ar = Aext + (size_t)m * KCAT;
    uint32_t hi = (uint32_t)bf_hi(h0) | ((uint32_t)bf_hi(h1) << 16);
    uint32_t lo = (uint32_t)bf_lo(h0) | ((uint32_t)bf_lo(h1) << 16);
    *(uint32_t*)(ar + d)        = hi;
    *(uint32_t*)(ar + 1024 + d) = lo;
    *(uint32_t*)(ar + 2048 + d) = hi;
}

// ---------------- online-softmax segment attention (single x pass) ---------
__global__ __launch_bounds__(256)
void attn_kernel(const float* __restrict__ x, const float* __restrict__ S,
                 const int* __restrict__ seg, __nv_bfloat16* __restrict__ Aext) {
    __shared__ float  sq[DIN];
    __shared__ float4 sred[8 * 128];
    __shared__ float  swm[8];
    __shared__ float  swd[8];

    const int b = blockIdx.x;
    const int tid = threadIdx.x;
    const int w = tid >> 5, lane = tid & 31;
    const int s = seg[b];
    const int e = seg[b + 1];

    for (int d = tid; d < DIN; d += 256) sq[d] = S[(size_t)b * DIN + d];  // q=h
    __syncthreads();

    const float4* q4 = (const float4*)sq;
    const float4 qa = q4[lane], qb = q4[32 + lane], qc = q4[64 + lane], qd = q4[96 + lane];

    float m = -INFINITY, den = 0.f;
    float4 aa = make_float4(0, 0, 0, 0), ab = aa, ac = aa, ad = aa;

    for (int n = s + w; n < e; n += 8) {
        const float4* xv = (const float4*)(x + (size_t)n * DIN);
        float4 xa = xv[lane], xb = xv[32 + lane], xc = xv[64 + lane], xd = xv[96 + lane];
        float p = xa.x * qa.x + xa.y * qa.y + xa.z * qa.z + xa.w * qa.w;
        p += xb.x * qb.x + xb.y * qb.y + xb.z * qb.z + xb.w * qb.w;
        p += xc.x * qc.x + xc.y * qc.y + xc.z * qc.z + xc.w * qc.w;
        p += xd.x * qd.x + xd.y * qd.y + xd.z * qd.z + xd.w * qd.w;
#pragma unroll
        for (int off = 16; off > 0; off >>= 1)
            p += __shfl_xor_sync(0xffffffffu, p, off);
        float mn = fmaxf(m, p);
        float sc = __expf(m - mn);
        float ex = __expf(p - mn);
        den = den * sc + ex;
        aa.x = aa.x * sc + ex * xa.x; aa.y = aa.y * sc + ex * xa.y;
        aa.z = aa.z * sc + ex * xa.z; aa.w = aa.w * sc + ex * xa.w;
        ab.x = ab.x * sc + ex * xb.x; ab.y = ab.y * sc + ex * xb.y;
        ab.z = ab.z * sc + ex * xb.z; ab.w = ab.w * sc + ex * xb.w;
        ac.x = ac.x * sc + ex * xc.x; ac.y = ac.y * sc + ex * xc.y;
        ac.z = ac.z * sc + ex * xc.z; ac.w = ac.w * sc + ex * xc.w;
        ad.x = ad.x * sc + ex * xd.x; ad.y = ad.y * sc + ex * xd.y;
        ad.z = ad.z * sc + ex * xd.z; ad.w = ad.w * sc + ex * xd.w;
        m = mn;
    }
    sred[w * 128 + lane]      = aa;
    sred[w * 128 + 32 + lane] = ab;
    sred[w * 128 + 64 + lane] = ac;
    sred[w * 128 + 96 + lane] = ad;
    if (lane == 0) { swm[w] = m; swd[w] = den; }
    __syncthreads();

    if (tid < 128) {
        float4 t = make_float4(0, 0, 0, 0);
        if (e > s) {
            float M = -INFINITY;
#pragma unroll
            for (int i = 0; i < 8; i++) M = fmaxf(M, swm[i]);
            float dtot = 0.f;
#pragma unroll
            for (int ww = 0; ww < 8; ww++) {
                float ws = __expf(swm[ww] - M);
                float4 v = sred[ww * 128 + tid];
                t.x += ws * v.x; t.y += ws * v.y;
                t.z += ws * v.z; t.w += ws * v.w;
                dtot += ws * swd[ww];
            }
            float inv = 1.0f / dtot;
            t.x *= inv; t.y *= inv; t.z *= inv; t.w *= inv;
        }
        // bf16x3 r-export into Aext cols 512+4*tid (+class offsets)
        __nv_bfloat16* ar = Aext + (size_t)b * KCAT + 512 + 4 * tid;
        uint2 hi, lo;
        hi.x = (uint32_t)bf_hi(t.x) | ((uint32_t)bf_hi(t.y) << 16);
        hi.y = (uint32_t)bf_hi(t.z) | ((uint32_t)bf_hi(t.w) << 16);
        lo.x = (uint32_t)bf_lo(t.x) | ((uint32_t)bf_lo(t.y) << 16);
        lo.y = (uint32_t)bf_lo(t.z) | ((uint32_t)bf_lo(t.w) << 16);
        *(uint2*)(ar)        = hi;
        *(uint2*)(ar + 1024) = lo;
        *(uint2*)(ar + 2048) = hi;
    }
}

// ---------------- launch ----------------------------------------------------
extern "C" void kernel_launch(void* const* d_in, const int* in_sizes, int n_in,
                              void* d_out, int out_size) {
    const float* x     = (const float*)d_in[0];
    const void*  batch = d_in[1];
    const float* Wih   = (const float*)d_in[2];
    const float* Whh   = (const float*)d_in[3];
    const float* bih   = (const float*)d_in[4];
    const float* bhh   = (const float*)d_in[5];
    const float* Wpost = (const float*)d_in[6];
    const float* bpost = (const float*)d_in[7];
    float*       out   = (float*)d_out;
    const int N = in_sizes[1];

    float *S, *c, *z, *bsum;
    int* seg;
    __nv_bfloat16 *Aext, *Bext, *Pext;
    cudaGetSymbolAddress((void**)&S,    g_S);
    cudaGetSymbolAddress((void**)&c,    g_c);
    cudaGetSymbolAddress((void**)&z,    g_z);
    cudaGetSymbolAddress((void**)&bsum, g_bsum);
    cudaGetSymbolAddress((void**)&seg,  g_seg);
    cudaGetSymbolAddress((void**)&Aext, g_Aext);
    cudaGetSymbolAddress((void**)&Bext, g_Bext);
    cudaGetSymbolAddress((void**)&Pext, g_Pext);

    cudaFuncSetAttribute(gemm_mma_kernel<false>,
                         cudaFuncAttributeMaxDynamicSharedMemorySize, SMEM3);
    cudaFuncSetAttribute(gemm_mma_kernel<true>,
                         cudaFuncAttributeMaxDynamicSharedMemorySize, SMEM3);

    // launch idx 0..2 = prep; idx 3 = first GEMM (ncu captures idx 3)
    prep_all_kernel<<<3848, 256>>>(Wih, Whh, Wpost, bih, bhh, Bext, Pext, bsum);
    seg_kernel<<<(N + 256) / 256, 256>>>(batch, N, seg);
    init_zero_kernel<<<(2 * BGRAPH * DIN + BGRAPH * KCAT / 2) / 256, 256>>>(
        S, c, (uint32_t*)Aext);

    for (int t = 0; t < TSTEPS; t++) {
        gemm_mma_kernel<false><<<dim3(NGATE / GBN, BGRAPH / GBM), 256, SMEM3>>>(
            Aext, Bext, bsum, z, NGATE);
        lstm_kernel<<<(BGRAPH * DIN / 2) / 256, 256>>>(z, c, S, Aext);
        attn_kernel<<<BGRAPH, 256>>>(x, S, seg, Aext);
    }
    gemm_mma_kernel<true><<<dim3(DIN / GBN, BGRAPH / GBM), 256, SMEM3>>>(
        Aext, Pext, bpost, out, DIN);
}

// round 16
// speedup vs baseline: 1.1936x; 1.0215x over previous
#include <cuda_runtime.h>
#include <cuda_bf16.h>
#include <math.h>
#include <stdint.h>

// Problem constants (fixed shapes from reference)
#define DIN    512
#define BGRAPH 1024
#define NGATE  2048   // 4*DIN
#define KDIM   1024   // 2*DIN
#define TSTEPS 6
#define KCAT   3072   // bf16x3 concatenated K

// ---------------- scratch (device globals; no allocation allowed) ----------
__device__ float g_bsum[NGATE];           // bih+bhh (natural gate layout)
__device__ float g_S[BGRAPH * DIN];       // h state (fp32, attn q reads)
__device__ float g_c[BGRAPH * DIN];       // cell state
__device__ float g_z[BGRAPH * NGATE];     // pre-activation gates
__device__ int   g_seg[BGRAPH + 1];       // segment boundaries
// Row-major bf16 split-cat operands [rows][3072]:
// A classes: [0,1024):hi(S=[h|r]) [1024,2048):lo(S) [2048,3072):hi(S)
// W classes: [0,1024):hi(W)       [1024,2048):hi(W) [2048,3072):lo(W)
__device__ __align__(128) __nv_bfloat16 g_Aext[BGRAPH * KCAT];  // 6 MB
__device__ __align__(128) __nv_bfloat16 g_Bext[NGATE * KCAT];   // 12 MB
__device__ __align__(128) __nv_bfloat16 g_Pext[DIN * KCAT];     // 3 MB

// ---------------- helpers ---------------------------------------------------
__device__ __forceinline__ uint32_t smem_u32(const void* p) {
    uint32_t a;
    asm("{ .reg .u64 t; cvta.to.shared.u64 t, %1; cvt.u32.u64 %0, t; }"
        : "=r"(a) : "l"(p));
    return a;
}
__device__ __forceinline__ uint32_t sw128(uint32_t off) {
    return off ^ ((off >> 3) & 0x70);
}
__device__ __forceinline__ void cp16(uint32_t dst, const void* src) {
    asm volatile("cp.async.cg.shared.global [%0], [%1], 16;"
                 :: "r"(dst), "l"(src));
}
#define CP_COMMIT() asm volatile("cp.async.commit_group;")
#define CP_WAIT2()  asm volatile("cp.async.wait_group 2;")
#define CP_WAIT1()  asm volatile("cp.async.wait_group 1;")
#define CP_WAIT0()  asm volatile("cp.async.wait_group 0;")
#define LDSM_X4(r0, r1, r2, r3, addr) \
    asm volatile("ldmatrix.sync.aligned.m8n8.x4.shared.b16 {%0,%1,%2,%3}, [%4];" \
        : "=r"(r0), "=r"(r1), "=r"(r2), "=r"(r3) : "r"(addr))
#define MMA16816(c, a, b0, b1) \
    asm volatile("mma.sync.aligned.m16n8k16.row.col.f32.bf16.bf16.f32 " \
        "{%0,%1,%2,%3}, {%4,%5,%6,%7}, {%8,%9}, {%0,%1,%2,%3};" \
        : "+f"((c)[0]), "+f"((c)[1]), "+f"((c)[2]), "+f"((c)[3]) \
        : "r"((a)[0]), "r"((a)[1]), "r"((a)[2]), "r"((a)[3]), "r"(b0), "r"(b1))

__device__ __forceinline__ unsigned short bf_hi(float v) {
    return __bfloat16_as_ushort(__float2bfloat16(v));
}
__device__ __forceinline__ unsigned short bf_lo(float v) {
    __nv_bfloat16 h = __float2bfloat16(v);
    return __bfloat16_as_ushort(__float2bfloat16(v - __bfloat162float(h)));
}

// ---------------- merged prep (ONE launch -> ncu idx 3 = first GEMM) -------
// blocks [0,3072): Bext (natural rows); [3072,3840): Pext; [3840,3848): bias
__global__ void prep_all_kernel(const float* __restrict__ Wih,
                                const float* __restrict__ Whh,
                                const float* __restrict__ Wpost,
                                const float* __restrict__ bih,
                                const float* __restrict__ bhh,
                                __nv_bfloat16* __restrict__ Bext,
                                __nv_bfloat16* __restrict__ Pext,
                                float* __restrict__ bsum) {
    int blk = blockIdx.x, tid = threadIdx.x;
    if (blk < 3072) {
        int idx = blk * 256 + tid;
        int row = idx / (KCAT / 8), j = idx % (KCAT / 8);
        int kc0 = j * 8, cls = kc0 >> 10, k0 = kc0 & 1023;
        const float* wr = Wih + (size_t)row * 1024 + k0;
        const float* hr = Whh + (size_t)row * 512;
        unsigned short u[8];
#pragma unroll
        for (int q = 0; q < 8; q++) {
            float v = wr[q];
            int k = k0 + q;
            if (k < 512) v += hr[k];
            u[q] = (cls < 2) ? bf_hi(v) : bf_lo(v);
        }
        uint4 pk;
        pk.x = (uint32_t)u[0] | ((uint32_t)u[1] << 16);
        pk.y = (uint32_t)u[2] | ((uint32_t)u[3] << 16);
        pk.z = (uint32_t)u[4] | ((uint32_t)u[5] << 16);
        pk.w = (uint32_t)u[6] | ((uint32_t)u[7] << 16);
        *(uint4*)(Bext + (size_t)row * KCAT + kc0) = pk;
    } else if (blk < 3840) {
        int idx = (blk - 3072) * 256 + tid;
        int row = idx / (KCAT / 8), j = idx % (KCAT / 8);
        int kc0 = j * 8, cls = kc0 >> 10, k0 = kc0 & 1023;
        const float* wr = Wpost + (size_t)row * 1024 + k0;
        unsigned short u[8];
#pragma unroll
        for (int q = 0; q < 8; q++) {
            float v = wr[q];
            u[q] = (cls < 2) ? bf_hi(v) : bf_lo(v);
        }
        uint4 pk;
        pk.x = (uint32_t)u[0] | ((uint32_t)u[1] << 16);
        pk.y = (uint32_t)u[2] | ((uint32_t)u[3] << 16);
        pk.z = (uint32_t)u[4] | ((uint32_t)u[5] << 16);
        pk.w = (uint32_t)u[6] | ((uint32_t)u[7] << 16);
        *(uint4*)(Pext + (size_t)row * KCAT + kc0) = pk;
    } else {
        int idx = (blk - 3840) * 256 + tid;
        if (idx < NGATE) bsum[idx] = bih[idx] + bhh[idx];
    }
}

// Boundary-scatter segment build; batch = int32 (JAX default) or int64.
__global__ void seg_kernel(const void* __restrict__ batchv, int n,
                           int* __restrict__ seg) {
    const int*       w32 = (const int*)batchv;
    const long long* w64 = (const long long*)batchv;
    const bool is64 = (w32[n - 1] == 0);
    int i = blockIdx.x * 256 + threadIdx.x;
    if (i > n) return;
    long long bi = (i < n) ? (is64 ? w64[i] : (long long)w32[i])
                           : (long long)BGRAPH;
    long long bp = (i > 0) ? (is64 ? w64[i - 1] : (long long)w32[i - 1])
                           : (long long)-1;
    for (long long b = bp + 1; b <= bi; b++) seg[b] = i;
}

// Zero S (0.5M f32), c (0.5M f32), Aext (1.5M u32 words) = 2.5M threads
__global__ void init_zero_kernel(float* __restrict__ S, float* __restrict__ c,
                                 uint32_t* __restrict__ Aw) {
    int idx = blockIdx.x * 256 + threadIdx.x;
    if (idx < BGRAPH * DIN)                  S[idx] = 0.f;
    else if (idx < 2 * BGRAPH * DIN)         c[idx - BGRAPH * DIN] = 0.f;
    else                                     Aw[idx - 2 * BGRAPH * DIN] = 0u;
}

// ---------------- mma.sync bf16 GEMM, 128x64x64, 4-stage / 1-sync ----------
// C[M,N] = Aext[M,KCAT] @ Bext[N,KCAT]^T + bias[N]  (opt ReLU)
// Prefetch issued AFTER the barrier: one __syncthreads per K-iter orders both
// stage-ready and stage-reuse; data requested 3 iterations ahead.
#define GBM 128
#define GBN 64
#define GBK 64
#define NKI (KCAT / GBK)          // 48
#define ASTAGE (GBM * GBK * 2)    // 16384 B
#define BSTAGE (GBN * GBK * 2)    // 8192 B
#define STG_STRIDE (ASTAGE + BSTAGE)   // 24576 B per stage
#define NSTG 4
#define SMEM4 (NSTG * STG_STRIDE)      // 98304 B dynamic

template <bool RELU>
__global__ __launch_bounds__(256, 2)
void gemm_mma_kernel(const __nv_bfloat16* __restrict__ Aext,
                     const __nv_bfloat16* __restrict__ Bx,
                     const float* __restrict__ bias, float* __restrict__ C,
                     int ldc) {
    extern __shared__ __align__(128) char sm4[];
    const int tid  = threadIdx.x;
    const int wid  = tid >> 5, lane = tid & 31;
    const int wm   = wid & 3;          // m-warp: rows wm*32..+32
    const int wn   = wid >> 2;         // n-warp: cols wn*32..+32
    const int bm   = blockIdx.y * GBM;
    const int bn   = blockIdx.x * GBN;
    const uint32_t sb = smem_u32(sm4);

    const __nv_bfloat16* Abase = Aext + (size_t)bm * KCAT;
    const __nv_bfloat16* Bbase = Bx  + (size_t)bn * KCAT;

    float acc[2][4][4] = {};

    const int arow = wm * 32 + (lane & 15);
    const int akb  = ((lane >> 4) & 1) * 16;
    const int nrow = wn * 32 + (lane & 7) + ((lane >> 4) & 1) * 8;
    const int nkb  = ((lane >> 3) & 1) * 16;

    const int ar4 = tid >> 3, ac4 = tid & 7;   // loader coords

    // prologue: stages 0..2 as separate commit groups
#pragma unroll
    for (int s = 0; s < 3; s++) {
        const uint32_t st = sb + s * STG_STRIDE;
        const __nv_bfloat16* An = Abase + s * GBK;
        const __nv_bfloat16* Bn = Bbase + s * GBK;
#pragma unroll
        for (int p = 0; p < 4; p++) {
            int r = p * 32 + ar4;
            cp16(st + sw128(r * 128 + ac4 * 16), An + (size_t)r * KCAT + ac4 * 8);
        }
#pragma unroll
        for (int p = 0; p < 2; p++) {
            int r = p * 32 + ar4;
            cp16(st + ASTAGE + sw128(r * 128 + ac4 * 16),
                 Bn + (size_t)r * KCAT + ac4 * 8);
        }
        CP_COMMIT();
    }

    int cur_s = 0;
    for (int i = 0; i < NKI; i++) {
        // stage i ready when ≤(groups beyond it) outstanding
        const int rem = NKI - 1 - i;
        if (rem >= 2)      { CP_WAIT2(); }
        else if (rem == 1) { CP_WAIT1(); }
        else               { CP_WAIT0(); }
        __syncthreads();   // also guarantees slot (cur_s+3)%4 fully consumed

        if (i + 3 < NKI) {
            const int ns = (cur_s + 3) & 3;
            const uint32_t st = sb + ns * STG_STRIDE;
            const __nv_bfloat16* An = Abase + (i + 3) * GBK;
            const __nv_bfloat16* Bn = Bbase + (i + 3) * GBK;
#pragma unroll
            for (int p = 0; p < 4; p++) {
                int r = p * 32 + ar4;
                cp16(st + sw128(r * 128 + ac4 * 16),
                     An + (size_t)r * KCAT + ac4 * 8);
            }
#pragma unroll
            for (int p = 0; p < 2; p++) {
                int r = p * 32 + ar4;
                cp16(st + ASTAGE + sw128(r * 128 + ac4 * 16),
                     Bn + (size_t)r * KCAT + ac4 * 8);
            }
            CP_COMMIT();
        }

        const uint32_t abase = sb + cur_s * STG_STRIDE;
        const uint32_t bbase = abase + ASTAGE;
#pragma unroll
        for (int kk = 0; kk < 4; kk++) {
            uint32_t af[2][4], bf[2][4];
#pragma unroll
            for (int mi = 0; mi < 2; mi++)
                LDSM_X4(af[mi][0], af[mi][1], af[mi][2], af[mi][3],
                        abase + sw128((arow + mi * 16) * 128 + kk * 32 + akb));
#pragma unroll
            for (int g = 0; g < 2; g++)
                LDSM_X4(bf[g][0], bf[g][1], bf[g][2], bf[g][3],
                        bbase + sw128((nrow + g * 16) * 128 + kk * 32 + nkb));
#pragma unroll
            for (int mi = 0; mi < 2; mi++)
#pragma unroll
                for (int nj = 0; nj < 4; nj++)
                    MMA16816(acc[mi][nj], af[mi],
                             bf[nj >> 1][(nj & 1) * 2], bf[nj >> 1][(nj & 1) * 2 + 1]);
        }
        cur_s = (cur_s + 1) & 3;
    }

    // ---- epilogue: bias (+ReLU), plain stores ----
#pragma unroll
    for (int mi = 0; mi < 2; mi++) {
#pragma unroll
        for (int nj = 0; nj < 4; nj++) {
            const int m0 = bm + wm * 32 + mi * 16 + (lane >> 2);
            const int cn = bn + wn * 32 + nj * 8 + 2 * (lane & 3);
            float b0 = __ldg(bias + cn), b1 = __ldg(bias + cn + 1);
            float v0 = acc[mi][nj][0] + b0, v1 = acc[mi][nj][1] + b1;
            float v2 = acc[mi][nj][2] + b0, v3 = acc[mi][nj][3] + b1;
            if (RELU) {
                v0 = fmaxf(v0, 0.f); v1 = fmaxf(v1, 0.f);
                v2 = fmaxf(v2, 0.f); v3 = fmaxf(v3, 0.f);
            }
            *(float2*)(C + (size_t)m0 * ldc + cn)       = make_float2(v0, v1);
            *(float2*)(C + (size_t)(m0 + 8) * ldc + cn) = make_float2(v2, v3);
        }
    }
}

// ---------------- LSTM cell + fused bf16x3 h-export (R11-proven) -----------
__global__ __launch_bounds__(256)
void lstm_kernel(const float* __restrict__ z, float* __restrict__ c,
                 float* __restrict__ S, __nv_bfloat16* __restrict__ Aext) {
    int T = blockIdx.x * 256 + threadIdx.x;     // < 262144
    int m = T >> 8, d = (T & 255) * 2;
    const float* zr = z + (size_t)m * NGATE;
    float2 zi = *(const float2*)(zr + d);
    float2 zf = *(const float2*)(zr + 512 + d);
    float2 zg = *(const float2*)(zr + 1024 + d);
    float2 zo = *(const float2*)(zr + 1536 + d);
    float2 cc = *(float2*)(c + (size_t)m * DIN + d);

    float si0 = 1.f / (1.f + __expf(-zi.x)), si1 = 1.f / (1.f + __expf(-zi.y));
    float sf0 = 1.f / (1.f + __expf(-zf.x)), sf1 = 1.f / (1.f + __expf(-zf.y));
    float so0 = 1.f / (1.f + __expf(-zo.x)), so1 = 1.f / (1.f + __expf(-zo.y));
    float cn0 = sf0 * cc.x + si0 * tanhf(zg.x);
    float cn1 = sf1 * cc.y + si1 * tanhf(zg.y);
    float h0 = so0 * tanhf(cn0);
    float h1 = so1 * tanhf(cn1);

    *(float2*)(c + (size_t)m * DIN + d) = make_float2(cn0, cn1);
    *(float2*)(S + (size_t)m * DIN + d) = make_float2(h0, h1);

    __nv_bfloat16* ar = Aext + (size_t)m * KCAT;
    uint32_t hi = (uint32_t)bf_hi(h0) | ((uint32_t)bf_hi(h1) << 16);
    uint32_t lo = (uint32_t)bf_lo(h0) | ((uint32_t)bf_lo(h1) << 16);
    *(uint32_t*)(ar + d)        = hi;
    *(uint32_t*)(ar + 1024 + d) = lo;
    *(uint32_t*)(ar + 2048 + d) = hi;
}

// ---------------- online-softmax segment attention (single x pass) ---------
__global__ __launch_bounds__(256)
void attn_kernel(const float* __restrict__ x, const float* __restrict__ S,
                 const int* __restrict__ seg, __nv_bfloat16* __restrict__ Aext) {
    __shared__ float  sq[DIN];
    __shared__ float4 sred[8 * 128];
    __shared__ float  swm[8];
    __shared__ float  swd[8];

    const int b = blockIdx.x;
    const int tid = threadIdx.x;
    const int w = tid >> 5, lane = tid & 31;
    const int s = seg[b];
    const int e = seg[b + 1];

    for (int d = tid; d < DIN; d += 256) sq[d] = S[(size_t)b * DIN + d];  // q=h
    __syncthreads();

    const float4* q4 = (const float4*)sq;
    const float4 qa = q4[lane], qb = q4[32 + lane], qc = q4[64 + lane], qd = q4[96 + lane];

    float m = -INFINITY, den = 0.f;
    float4 aa = make_float4(0, 0, 0, 0), ab = aa, ac = aa, ad = aa;

    for (int n = s + w; n < e; n += 8) {
        const float4* xv = (const float4*)(x + (size_t)n * DIN);
        float4 xa = xv[lane], xb = xv[32 + lane], xc = xv[64 + lane], xd = xv[96 + lane];
        float p = xa.x * qa.x + xa.y * qa.y + xa.z * qa.z + xa.w * qa.w;
        p += xb.x * qb.x + xb.y * qb.y + xb.z * qb.z + xb.w * qb.w;
        p += xc.x * qc.x + xc.y * qc.y + xc.z * qc.z + xc.w * qc.w;
        p += xd.x * qd.x + xd.y * qd.y + xd.z * qd.z + xd.w * qd.w;
#pragma unroll
        for (int off = 16; off > 0; off >>= 1)
            p += __shfl_xor_sync(0xffffffffu, p, off);
        float mn = fmaxf(m, p);
        float sc = __expf(m - mn);
        float ex = __expf(p - mn);
        den = den * sc + ex;
        aa.x = aa.x * sc + ex * xa.x; aa.y = aa.y * sc + ex * xa.y;
        aa.z = aa.z * sc + ex * xa.z; aa.w = aa.w * sc + ex * xa.w;
        ab.x = ab.x * sc + ex * xb.x; ab.y = ab.y * sc + ex * xb.y;
        ab.z = ab.z * sc + ex * xb.z; ab.w = ab.w * sc + ex * xb.w;
        ac.x = ac.x * sc + ex * xc.x; ac.y = ac.y * sc + ex * xc.y;
        ac.z = ac.z * sc + ex * xc.z; ac.w = ac.w * sc + ex * xc.w;
        ad.x = ad.x * sc + ex * xd.x; ad.y = ad.y * sc + ex * xd.y;
        ad.z = ad.z * sc + ex * xd.z; ad.w = ad.w * sc + ex * xd.w;
        m = mn;
    }
    sred[w * 128 + lane]      = aa;
    sred[w * 128 + 32 + lane] = ab;
    sred[w * 128 + 64 + lane] = ac;
    sred[w * 128 + 96 + lane] = ad;
    if (lane == 0) { swm[w] = m; swd[w] = den; }
    __syncthreads();

    if (tid < 128) {
        float4 t = make_float4(0, 0, 0, 0);
        if (e > s) {
            float M = -INFINITY;
#pragma unroll
            for (int i = 0; i < 8; i++) M = fmaxf(M, swm[i]);
            float dtot = 0.f;
#pragma unroll
            for (int ww = 0; ww < 8; ww++) {
                float ws = __expf(swm[ww] - M);
                float4 v = sred[ww * 128 + tid];
                t.x += ws * v.x; t.y += ws * v.y;
                t.z += ws * v.z; t.w += ws * v.w;
                dtot += ws * swd[ww];
            }
            float inv = 1.0f / dtot;
            t.x *= inv; t.y *= inv; t.z *= inv; t.w *= inv;
        }
        // bf16x3 r-export into Aext cols 512+4*tid (+class offsets)
        __nv_bfloat16* ar = Aext + (size_t)b * KCAT + 512 + 4 * tid;
        uint2 hi, lo;
        hi.x = (uint32_t)bf_hi(t.x) | ((uint32_t)bf_hi(t.y) << 16);
        hi.y = (uint32_t)bf_hi(t.z) | ((uint32_t)bf_hi(t.w) << 16);
        lo.x = (uint32_t)bf_lo(t.x) | ((uint32_t)bf_lo(t.y) << 16);
        lo.y = (uint32_t)bf_lo(t.z) | ((uint32_t)bf_lo(t.w) << 16);
        *(uint2*)(ar)        = hi;
        *(uint2*)(ar + 1024) = lo;
        *(uint2*)(ar + 2048) = hi;
    }
}

// ---------------- launch ----------------------------------------------------
extern "C" void kernel_launch(void* const* d_in, const int* in_sizes, int n_in,
                              void* d_out, int out_size) {
    const float* x     = (const float*)d_in[0];
    const void*  batch = d_in[1];
    const float* Wih   = (const float*)d_in[2];
    const float* Whh   = (const float*)d_in[3];
    const float* bih   = (const float*)d_in[4];
    const float* bhh   = (const float*)d_in[5];
    const float* Wpost = (const float*)d_in[6];
    const float* bpost = (const float*)d_in[7];
    float*       out   = (float*)d_out;
    const int N = in_sizes[1];

    float *S, *c, *z, *bsum;
    int* seg;
    __nv_bfloat16 *Aext, *Bext, *Pext;
    cudaGetSymbolAddress((void**)&S,    g_S);
    cudaGetSymbolAddress((void**)&c,    g_c);
    cudaGetSymbolAddress((void**)&z,    g_z);
    cudaGetSymbolAddress((void**)&bsum, g_bsum);
    cudaGetSymbolAddress((void**)&seg,  g_seg);
    cudaGetSymbolAddress((void**)&Aext, g_Aext);
    cudaGetSymbolAddress((void**)&Bext, g_Bext);
    cudaGetSymbolAddress((void**)&Pext, g_Pext);

    cudaFuncSetAttribute(gemm_mma_kernel<false>,
                         cudaFuncAttributeMaxDynamicSharedMemorySize, SMEM4);
    cudaFuncSetAttribute(gemm_mma_kernel<true>,
                         cudaFuncAttributeMaxDynamicSharedMemorySize, SMEM4);

    // launch idx 0..2 = prep; idx 3 = first GEMM (ncu captures idx 3)
    prep_all_kernel<<<3848, 256>>>(Wih, Whh, Wpost, bih, bhh, Bext, Pext, bsum);
    seg_kernel<<<(N + 256) / 256, 256>>>(batch, N, seg);
    init_zero_kernel<<<(2 * BGRAPH * DIN + BGRAPH * KCAT / 2) / 256, 256>>>(
        S, c, (uint32_t*)Aext);

    for (int t = 0; t < TSTEPS; t++) {
        gemm_mma_kernel<false><<<dim3(NGATE / GBN, BGRAPH / GBM), 256, SMEM4>>>(
            Aext, Bext, bsum, z, NGATE);
        lstm_kernel<<<(BGRAPH * DIN / 2) / 256, 256>>>(z, c, S, Aext);
        attn_kernel<<<BGRAPH, 256>>>(x, S, seg, Aext);
    }
    gemm_mma_kernel<true><<<dim3(DIN / GBN, BGRAPH / GBM), 256, SMEM4>>>(
        Aext, Pext, bpost, out, DIN);
}